// round 2
// baseline (speedup 1.0000x reference)
#include <cuda_runtime.h>
#include <math.h>

// out[n, e] = tanh( sum_d x[n, d] * trans[u[n], d, e] + bias[u[n], e] )
// B=16, S=256 -> N=4096 tokens; D=256; U=2000 matrices of 256KB each.
//
// Strategy: counting-sort tokens by URL so each distinct matrix is read from
// DRAM exactly once (one CTA per URL, matrix rows broadcast-FMA'd into all
// tokens of that URL). Traffic: ~1742 distinct * 256KB ~= 457MB vs 1.07GB naive.

#define DDIM 256
#define DV 64          // DDIM / 4 (float4 per row)
#define NTHREADS 64    // one float4 (4 output cols) per thread
#define MAXU 2048
#define MAXN 8192
#define MCAP 8         // max tokens per URL handled per pass

__device__ int g_count[MAXU];
__device__ int g_offset[MAXU + 1];
__device__ int g_cursor[MAXU];
__device__ int g_order[MAXN];

__global__ void k_zero(int U) {
    int i = blockIdx.x * blockDim.x + threadIdx.x;
    if (i < U) g_count[i] = 0;
}

__global__ void k_hist(const int* __restrict__ urls, int N) {
    int i = blockIdx.x * blockDim.x + threadIdx.x;
    if (i < N) atomicAdd(&g_count[urls[i]], 1);
}

// Single-CTA exclusive scan over up to 2048 bins (256 threads x 8 bins each).
__global__ void k_scan(int U) {
    __shared__ int s[256];
    int t = threadIdx.x;
    int base = t * 8;
    int local[8];
    int sum = 0;
#pragma unroll
    for (int k = 0; k < 8; k++) {
        int c = (base + k < U) ? g_count[base + k] : 0;
        local[k] = sum;
        sum += c;
    }
    s[t] = sum;
    __syncthreads();
    for (int off = 1; off < 256; off <<= 1) {
        int v = (t >= off) ? s[t - off] : 0;
        __syncthreads();
        s[t] += v;
        __syncthreads();
    }
    int pre = (t > 0) ? s[t - 1] : 0;
#pragma unroll
    for (int k = 0; k < 8; k++) {
        int idx = base + k;
        if (idx < U) {
            int o = pre + local[k];
            g_offset[idx] = o;
            g_cursor[idx] = o;
        }
    }
    if (t == 255) g_offset[U] = s[255];
}

__global__ void k_scatter(const int* __restrict__ urls, int N) {
    int i = blockIdx.x * blockDim.x + threadIdx.x;
    if (i < N) {
        int u = urls[i];
        int pos = atomicAdd(&g_cursor[u], 1);
        g_order[pos] = i;
    }
}

// Templated on group size so the hot loop issues only real FMAs (no dead
// predicated work for the common m~2 case).
template <int MC>
__device__ __forceinline__ void dot_loop(const float4* __restrict__ T4, int t,
                                         const float (*sx)[DDIM], float4* acc) {
#pragma unroll
    for (int j = 0; j < MC; j++) acc[j] = make_float4(0.f, 0.f, 0.f, 0.f);
#pragma unroll 4
    for (int d = 0; d < DDIM; d++) {
        float4 w = __ldg(&T4[d * DV + t]);
#pragma unroll
        for (int j = 0; j < MC; j++) {
            float xv = sx[j][d];
            acc[j].x = fmaf(xv, w.x, acc[j].x);
            acc[j].y = fmaf(xv, w.y, acc[j].y);
            acc[j].z = fmaf(xv, w.z, acc[j].z);
            acc[j].w = fmaf(xv, w.w, acc[j].w);
        }
    }
}

__global__ __launch_bounds__(NTHREADS) void k_main(
    const float* __restrict__ x, const float* __restrict__ trans,
    const float* __restrict__ bias, float* __restrict__ out) {
    int u = blockIdx.x;
    int start = g_offset[u];
    int end = g_offset[u + 1];
    if (start >= end) return;  // ~13% of URLs have no tokens
    int t = threadIdx.x;

    __shared__ float sx[MCAP][DDIM];
    __shared__ int stok[MCAP];

    const float4* T4 = (const float4*)(trans + (size_t)u * DDIM * DDIM);
    float4 bb = ((const float4*)(bias + (size_t)u * DDIM))[t];

    for (int base = start; base < end; base += MCAP) {
        int mc = min(MCAP, end - base);
        if (t < mc) stok[t] = g_order[base + t];
        __syncthreads();
        for (int j = 0; j < mc; j++) {
            const float4* xr = (const float4*)(x + (size_t)stok[j] * DDIM);
            reinterpret_cast<float4*>(sx[j])[t] = xr[t];
        }
        __syncthreads();

        float4 acc[MCAP];
        switch (mc) {
            case 1: dot_loop<1>(T4, t, sx, acc); break;
            case 2: dot_loop<2>(T4, t, sx, acc); break;
            case 3: dot_loop<3>(T4, t, sx, acc); break;
            case 4: dot_loop<4>(T4, t, sx, acc); break;
            case 5: dot_loop<5>(T4, t, sx, acc); break;
            case 6: dot_loop<6>(T4, t, sx, acc); break;
            case 7: dot_loop<7>(T4, t, sx, acc); break;
            default: dot_loop<8>(T4, t, sx, acc); break;
        }

        for (int j = 0; j < mc; j++) {
            float4 o;
            o.x = tanhf(acc[j].x + bb.x);
            o.y = tanhf(acc[j].y + bb.y);
            o.z = tanhf(acc[j].z + bb.z);
            o.w = tanhf(acc[j].w + bb.w);
            reinterpret_cast<float4*>(out + (size_t)stok[j] * DDIM)[t] = o;
        }
        __syncthreads();  // protect sx/stok reuse next pass
    }
}

extern "C" void kernel_launch(void* const* d_in, const int* in_sizes, int n_in,
                              void* d_out, int out_size) {
    const float* x     = (const float*)d_in[0];   // [B, S, D] fp32
    const int*   urls  = (const int*)d_in[1];     // [B, S] int32
    const float* trans = (const float*)d_in[2];   // [U, D, D] fp32
    const float* bias  = (const float*)d_in[3];   // [U, D] fp32
    float* out = (float*)d_out;

    int N = in_sizes[1];            // B*S tokens
    int U = in_sizes[3] / DDIM;     // number of URL matrices

    k_zero<<<(U + 255) / 256, 256>>>(U);
    k_hist<<<(N + 255) / 256, 256>>>(urls, N);
    k_scan<<<1, 256>>>(U);
    k_scatter<<<(N + 255) / 256, 256>>>(urls, N);
    k_main<<<U, NTHREADS>>>(x, trans, bias, out);
}

// round 3
// speedup vs baseline: 1.5408x; 1.5408x over previous
#include <cuda_runtime.h>
#include <math.h>

// out[n, e] = tanh( sum_d x[n, d] * trans[u[n], d, e] + bias[u[n], e] )
// N=4096 tokens, D=256, U=2000 matrices (256KB each).
// Counting-sort tokens by URL; one CTA per URL reads its matrix exactly once.

#define DDIM 256
#define DV 64          // DDIM/4 float4 per matrix row
#define NTH 128        // 4 warps: 2 row-groups x 64 col-threads
#define MAXU 2048
#define MAXN 8192
#define MCAP 8         // tokens per URL per pass

__device__ int g_offset[MAXU + 1];
__device__ int g_order[MAXN];

// ---- fused prep: histogram + scan + scatter, one CTA of 1024 threads ----
__global__ void k_prep(const int* __restrict__ urls, int N, int U) {
    __shared__ int cnt[MAXU];     // counts, then reused as scatter cursors
    __shared__ int ss[1024];
    int t = threadIdx.x;

    for (int i = t; i < MAXU; i += 1024) cnt[i] = 0;
    __syncthreads();
    for (int i = t; i < N; i += 1024) atomicAdd(&cnt[urls[i]], 1);
    __syncthreads();

    // inclusive scan over 1024 partials (2 bins per thread)
    int b0 = cnt[2 * t], b1 = cnt[2 * t + 1];
    ss[t] = b0 + b1;
    __syncthreads();
    for (int off = 1; off < 1024; off <<= 1) {
        int v = (t >= off) ? ss[t - off] : 0;
        __syncthreads();
        ss[t] += v;
        __syncthreads();
    }
    int pre = t ? ss[t - 1] : 0;
    int o0 = pre, o1 = pre + b0;
    if (2 * t < U)     g_offset[2 * t] = o0;
    if (2 * t + 1 < U) g_offset[2 * t + 1] = o1;
    if (t == 1023)     g_offset[U] = ss[1023];
    __syncthreads();
    cnt[2 * t] = o0;              // reuse as cursors
    cnt[2 * t + 1] = o1;
    __syncthreads();
    for (int i = t; i < N; i += 1024) {
        int pos = atomicAdd(&cnt[urls[i]], 1);
        g_order[pos] = i;
    }
}

// ---- main: one CTA per URL; thread (rg, tc): rg = d-half, tc = col group ----
template <int MC>
__device__ __forceinline__ void dot_loop(const float4* __restrict__ Tp, int tc,
                                         int dbase, const float (*sx)[DDIM],
                                         float4* acc) {
#pragma unroll
    for (int j = 0; j < MC; j++) acc[j] = make_float4(0.f, 0.f, 0.f, 0.f);
#pragma unroll 8
    for (int d0 = 0; d0 < DDIM / 2; d0++) {
        float4 w = __ldg(&Tp[d0 * DV + tc]);
#pragma unroll
        for (int j = 0; j < MC; j++) {
            float xv = sx[j][dbase + d0];
            acc[j].x = fmaf(xv, w.x, acc[j].x);
            acc[j].y = fmaf(xv, w.y, acc[j].y);
            acc[j].z = fmaf(xv, w.z, acc[j].z);
            acc[j].w = fmaf(xv, w.w, acc[j].w);
        }
    }
}

__global__ __launch_bounds__(NTH) void k_main(
    const float* __restrict__ x, const float* __restrict__ trans,
    const float* __restrict__ bias, float* __restrict__ out) {
    int u = blockIdx.x;
    int start = g_offset[u];
    int end = g_offset[u + 1];
    if (start >= end) return;

    int t = threadIdx.x;
    int tc = t & 63;      // output column group (float4)
    int rg = t >> 6;      // which half of d

    __shared__ float sx[MCAP][DDIM];   // 8KB; reused as reduction buffer
    __shared__ int stok[MCAP];

    const float4* T4 = (const float4*)(trans + (size_t)u * DDIM * DDIM);
    const float4* Tp = T4 + (size_t)rg * (DDIM / 2) * DV;
    int dbase = rg * (DDIM / 2);
    float4 bb = ((const float4*)(bias + (size_t)u * DDIM))[tc];

    for (int base = start; base < end; base += MCAP) {
        int mc = min(MCAP, end - base);
        if (t < mc) stok[t] = g_order[base + t];
        __syncthreads();
        for (int idx = t; idx < mc * DV; idx += NTH) {
            int j = idx >> 6, c = idx & 63;
            reinterpret_cast<float4*>(sx[j])[c] =
                ((const float4*)(x + (size_t)stok[j] * DDIM))[c];
        }
        __syncthreads();

        float4 acc[MCAP];
        switch (mc) {
            case 1: dot_loop<1>(Tp, tc, dbase, sx, acc); break;
            case 2: dot_loop<2>(Tp, tc, dbase, sx, acc); break;
            case 3: dot_loop<3>(Tp, tc, dbase, sx, acc); break;
            case 4: dot_loop<4>(Tp, tc, dbase, sx, acc); break;
            case 5: dot_loop<5>(Tp, tc, dbase, sx, acc); break;
            case 6: dot_loop<6>(Tp, tc, dbase, sx, acc); break;
            case 7: dot_loop<7>(Tp, tc, dbase, sx, acc); break;
            default: dot_loop<8>(Tp, tc, dbase, sx, acc); break;
        }

        // cross-rowgroup reduction through the sx buffer (done with sx now)
        __syncthreads();
        float4* sred = reinterpret_cast<float4*>(&sx[0][0]);  // MCAP*64 float4
        if (rg == 1) {
            for (int j = 0; j < mc; j++) sred[j * DV + tc] = acc[j];
        }
        __syncthreads();
        if (rg == 0) {
            for (int j = 0; j < mc; j++) {
                float4 p = sred[j * DV + tc];
                float4 o;
                o.x = tanhf(acc[j].x + p.x + bb.x);
                o.y = tanhf(acc[j].y + p.y + bb.y);
                o.z = tanhf(acc[j].z + p.z + bb.z);
                o.w = tanhf(acc[j].w + p.w + bb.w);
                reinterpret_cast<float4*>(out + (size_t)stok[j] * DDIM)[tc] = o;
            }
        }
        __syncthreads();
    }
}

extern "C" void kernel_launch(void* const* d_in, const int* in_sizes, int n_in,
                              void* d_out, int out_size) {
    const float* x     = (const float*)d_in[0];   // [B,S,D] fp32
    const int*   urls  = (const int*)d_in[1];     // [B,S] int32
    const float* trans = (const float*)d_in[2];   // [U,D,D] fp32
    const float* bias  = (const float*)d_in[3];   // [U,D] fp32
    float* out = (float*)d_out;

    int N = in_sizes[1];
    int U = in_sizes[3] / DDIM;

    k_prep<<<1, 1024>>>(urls, N, U);
    k_main<<<U, NTH>>>(x, trans, bias, out);
}